// round 14
// baseline (speedup 1.0000x reference)
#include <cuda_runtime.h>

#define NLAYERS 7
#define EPS_F 1e-5f

// Shapes (fixed by setup_inputs): bsz=8, C=8, QL=KL=128, A=8, cross_range=2
// pw / out: [64, 1024, 1024] f32;  conv_w: [7,8,8,1,3]; conv_b: [7,8]; prelu_a: [7]
//
// CTA r: (a) computes region r = (b, q) conv/band; (b) zero-fills the LINEAR
// 256KB chunk r of the output (64 consecutive 4KB rows), skipping live band
// float4s (|k - q_row| in {1,2}), so the global zero sweep is memset-shaped
// (adjacent CTAs write adjacent memory). Zero/band address sets are disjoint
// -> no cross-CTA ordering. Zero slices interleaved one per conv layer.

__device__ __forceinline__ void stcs4(float* p, float4 v) {
    asm volatile("st.global.cs.v4.f32 [%0], {%1,%2,%3,%4};"
                 :: "l"(p), "f"(v.x), "f"(v.y), "f"(v.z), "f"(v.w) : "memory");
}

__global__ __launch_bounds__(256, 5)
void sag_lin(const float* __restrict__ pw,
             const float* __restrict__ conv_w,
             const float* __restrict__ conv_b,
             const float* __restrict__ prelu_a,
             float* __restrict__ out)
{
    __shared__ float4 sW4[NLAYERS][8][8];   // [l][ci][co] = (k0,k1,k2,_)
    __shared__ float  sB [NLAYERS][8];
    __shared__ float  sA [NLAYERS];
    __shared__ float  sPS[4][8][8];         // partial row sums [pp][hh][co]
    __shared__ float  sInv[8][8];           // 1/(rowsum+eps)   [hh][co]

    const int tid  = threadIdx.x;
    const int lane = tid & 31;
    const int wrp  = tid >> 5;              // warp id 0..7
    const int bid  = blockIdx.x;
    const int b = bid >> 7;                 // batch   (compute role)
    const int i = bid & 127;                // query   (compute role)

    // ---- linear zero-chunk role ----
    // chunk = 64 rows; slice s, warp wrp owns global row bid*64 + s*8 + wrp.
    // that row's query index: q_s = (bid*8 + s) & 127  (since rows per q = 8)
    const int kl = lane >> 1;               // k contribution of lane
    float* zbase = out + ((size_t)bid << 16) + (size_t)wrp * 1024 + lane * 4;
    const float4 z = make_float4(0.f, 0.f, 0.f, 0.f);

    // compute roles: slab = pp*8+hh (8 lanes per slab), co = lane&7
    const int co   = tid & 7;
    const int pp   = tid >> 6;
    const int hh   = (tid >> 3) & 7;
    const int doff = (pp < 2) ? (pp - 2) : (pp - 1);  // {-2,-1,1,2}
    const int j    = i + doff;
    const bool pvalid = (j >= 0) && (j < 128);

    // ---- x load issued first ----
    float4 v0 = make_float4(0.f,0.f,0.f,0.f), v1 = v0;
    if (pvalid) {
        const float* srcx = pw +
            ((size_t)((b * 8 + co) * 1024 + (i * 8 + hh)) * 1024 + (size_t)j * 8);
        v0 = *(const float4*)srcx;
        v1 = *(const float4*)(srcx + 4);
    }

    // ---- zero slice 0 ----
    {
        const int qs = (bid * 8 + 0) & 127;
        #pragma unroll
        for (int g = 0; g < 8; g++) {
            const int dd = g * 16 + kl - qs;
            if (!((dd == 1) | (dd == -1) | (dd == 2) | (dd == -2)))
                stcs4(zbase + g * 128, z);
        }
    }

    // ---- conv params -> SMEM ----
    for (int t = tid; t < NLAYERS * 64; t += 256) {
        const int l = t >> 6, rem = t & 63, wco = rem >> 3, wci = rem & 7;
        const float* s = conv_w + ((l * 8 + wco) * 8 + wci) * 3;
        sW4[l][wci][wco] = make_float4(s[0], s[1], s[2], 0.f);
    }
    if (tid < NLAYERS * 8) (&sB[0][0])[tid] = conv_b[tid];
    if (tid < NLAYERS)     sA[tid] = prelu_a[tid];
    __syncthreads();

    float x[8] = {v0.x, v0.y, v0.z, v0.w, v1.x, v1.y, v1.z, v1.w};
    float c[8];
    #pragma unroll
    for (int w = 0; w < 8; w++) c[w] = x[w];

    const int gbase = lane & 24;            // slab group base lane

    // ---- 7-layer residual conv, rolling 3-reg shuffle window ----
    #pragma unroll 1
    for (int l = 0; l < NLAYERS; l++) {
        const float bias = sB[l][co];
        float acc[8];
        #pragma unroll
        for (int w = 0; w < 8; w++) acc[w] = bias;

        #pragma unroll
        for (int ci = 0; ci < 8; ci++) {
            const float4 wv = sW4[l][ci][co];
            const int src = gbase | ci;
            float ra = __shfl_sync(0xffffffffu, c[0], src);
            float rb = __shfl_sync(0xffffffffu, c[1], src);
            acc[0] += wv.y * ra + wv.z * rb;
            #pragma unroll
            for (int w = 1; w < 7; w++) {
                const float rc = __shfl_sync(0xffffffffu, c[w + 1], src);
                acc[w] += wv.x * ra + wv.y * rb + wv.z * rc;
                ra = rb; rb = rc;
            }
            acc[7] += wv.x * ra + wv.y * rb;
        }

        // interleaved zero slice l+1 (linear chunk row, band holes skipped)
        {
            const int s = l + 1;
            const int qs = (bid * 8 + s) & 127;
            float* p = zbase + (size_t)s * 8192;   // 8 rows * 1024 floats
            #pragma unroll
            for (int g = 0; g < 8; g++) {
                const int dd = g * 16 + kl - qs;
                if (!((dd == 1) | (dd == -1) | (dd == 2) | (dd == -2)))
                    stcs4(p + g * 128, z);
            }
        }

        const float pa = sA[l];
        #pragma unroll
        for (int w = 0; w < 8; w++) {
            const float y = (acc[w] >= 0.f) ? acc[w] : pa * acc[w];
            c[w] = y + c[w];                // residual, in place
        }
    }

    // ---- we = exp(relu(x - sigmoid(conv)))-1, masked; reuse x[] ----
    float partial = 0.f;
    #pragma unroll
    for (int w = 0; w < 8; w++) {
        const float sg = 1.f / (1.f + __expf(-c[w]));
        float sp = fmaxf(x[w] - sg, 0.f);
        if (hh == w) sp = 0.f;              // self mask
        float v = __expf(sp) - 1.f;         // sp >= 0
        if (!pvalid) v = 0.f;
        x[w] = v;
        partial += v;
    }
    sPS[pp][hh][co] = partial;
    __syncthreads();

    if (tid < 64) {
        const int th = tid >> 3, tc = tid & 7;
        const float s = sPS[0][th][tc] + sPS[1][th][tc] + sPS[2][th][tc] + sPS[3][th][tc];
        sInv[th][tc] = 1.f / (s + EPS_F);
    }
    __syncthreads();

    // ---- band store (addresses never touched by any zero path) ----
    if (pvalid) {
        const float inv = sInv[hh][co];
        float* dst = out +
            ((size_t)((b * 8 + co) * 1024 + (i * 8 + hh)) * 1024 + (size_t)j * 8);
        stcs4(dst,     make_float4(x[0]*inv, x[1]*inv, x[2]*inv, x[3]*inv));
        stcs4(dst + 4, make_float4(x[4]*inv, x[5]*inv, x[6]*inv, x[7]*inv));
    }
}

extern "C" void kernel_launch(void* const* d_in, const int* in_sizes, int n_in,
                              void* d_out, int out_size) {
    const float* pw = (const float*)d_in[0];
    const float* cw = (const float*)d_in[1];
    const float* cb = (const float*)d_in[2];
    const float* pa = (const float*)d_in[3];
    sag_lin<<<1024, 256>>>(pw, cw, cb, pa, (float*)d_out);
}

// round 15
// speedup vs baseline: 1.0825x; 1.0825x over previous
#include <cuda_runtime.h>

#define NLAYERS 7
#define EPS_F 1e-5f

// Shapes (fixed by setup_inputs): bsz=8, C=8, QL=KL=128, A=8, cross_range=2
// pw / out: [64, 1024, 1024] f32;  conv_w: [7,8,8,1,3]; conv_b: [7,8]; prelu_a: [7]
//
// One CTA per (b, q). Register-resident 7-layer residual conv via __shfl_sync.
// Zero fill is ROW-SEQUENTIAL (memset-shaped) using 256-bit v8 stores
// (sm_100+): warp w in slice s streams the full 4KB output row (channel s,
// agent-row w) as 4 contiguous 1KB warp-stores. Slices interleaved one per
// conv layer. Band values overwrite their 8 floats (one v8 store) after the
// __syncthreads (same-CTA cross-thread store ordering via barrier).

__device__ __forceinline__ void stz8(float* p) {
    asm volatile("st.global.cs.v8.b32 [%0], {%1,%1,%1,%1,%1,%1,%1,%1};"
                 :: "l"(p), "r"(0u) : "memory");
}
__device__ __forceinline__ void stcs8(float* p,
                                      float a0, float a1, float a2, float a3,
                                      float a4, float a5, float a6, float a7) {
    asm volatile("st.global.cs.v8.b32 [%0], {%1,%2,%3,%4,%5,%6,%7,%8};"
                 :: "l"(p),
                    "r"(__float_as_uint(a0)), "r"(__float_as_uint(a1)),
                    "r"(__float_as_uint(a2)), "r"(__float_as_uint(a3)),
                    "r"(__float_as_uint(a4)), "r"(__float_as_uint(a5)),
                    "r"(__float_as_uint(a6)), "r"(__float_as_uint(a7))
                 : "memory");
}

__global__ __launch_bounds__(256, 5)
void sag_v8(const float* __restrict__ pw,
            const float* __restrict__ conv_w,
            const float* __restrict__ conv_b,
            const float* __restrict__ prelu_a,
            float* __restrict__ out)
{
    __shared__ float4 sW4[NLAYERS][8][8];   // [l][ci][co] = (k0,k1,k2,_)
    __shared__ float  sB [NLAYERS][8];
    __shared__ float  sA [NLAYERS];
    __shared__ float  sPS[4][8][8];         // partial row sums [pp][hh][co]
    __shared__ float  sInv[8][8];           // 1/(rowsum+eps)   [hh][co]

    const int tid  = threadIdx.x;
    const int lane = tid & 31;
    const int wrp  = tid >> 5;              // warp id 0..7
    const int b = blockIdx.x >> 7;          // batch
    const int i = blockIdx.x & 127;         // query index
    const size_t base = ((size_t)(b * 8) * 1024 + (size_t)i * 8) * 1024;

    // zero-stream base: warp wrp owns row (channel s, agent-row wrp);
    // lane covers 8 floats (32B); 4 warp-stores of 256 floats cover the 4KB row
    float* zrow0 = out + base + (size_t)wrp * 1024 + lane * 8;

    // compute roles: slab = pp*8+hh (8 lanes per slab), co = lane&7
    const int co   = tid & 7;
    const int pp   = tid >> 6;
    const int hh   = (tid >> 3) & 7;
    const int doff = (pp < 2) ? (pp - 2) : (pp - 1);  // {-2,-1,1,2}
    const int j    = i + doff;
    const bool pvalid = (j >= 0) && (j < 128);

    // ---- x load issued first ----
    float4 v0 = make_float4(0.f,0.f,0.f,0.f), v1 = v0;
    if (pvalid) {
        const float* srcx = pw +
            ((size_t)((b * 8 + co) * 1024 + (i * 8 + hh)) * 1024 + (size_t)j * 8);
        v0 = *(const float4*)srcx;
        v1 = *(const float4*)(srcx + 4);
    }

    // ---- zero slice 0: channel 0, full 4KB row per warp, sequential v8 ----
    {
        float* p = zrow0;
        #pragma unroll
        for (int g = 0; g < 4; g++) stz8(p + g * 256);
    }

    // ---- conv params -> SMEM ----
    for (int t = tid; t < NLAYERS * 64; t += 256) {
        const int l = t >> 6, rem = t & 63, wco = rem >> 3, wci = rem & 7;
        const float* s = conv_w + ((l * 8 + wco) * 8 + wci) * 3;
        sW4[l][wci][wco] = make_float4(s[0], s[1], s[2], 0.f);
    }
    if (tid < NLAYERS * 8) (&sB[0][0])[tid] = conv_b[tid];
    if (tid < NLAYERS)     sA[tid] = prelu_a[tid];
    __syncthreads();

    float x[8] = {v0.x, v0.y, v0.z, v0.w, v1.x, v1.y, v1.z, v1.w};
    float c[8];
    #pragma unroll
    for (int w = 0; w < 8; w++) c[w] = x[w];

    const int gbase = lane & 24;            // slab group base lane

    // ---- 7-layer residual conv, rolling 3-reg shuffle window ----
    #pragma unroll 1
    for (int l = 0; l < NLAYERS; l++) {
        const float bias = sB[l][co];
        float acc[8];
        #pragma unroll
        for (int w = 0; w < 8; w++) acc[w] = bias;

        #pragma unroll
        for (int ci = 0; ci < 8; ci++) {
            const float4 wv = sW4[l][ci][co];
            const int src = gbase | ci;
            float ra = __shfl_sync(0xffffffffu, c[0], src);
            float rb = __shfl_sync(0xffffffffu, c[1], src);
            acc[0] += wv.y * ra + wv.z * rb;
            #pragma unroll
            for (int w = 1; w < 7; w++) {
                const float rc = __shfl_sync(0xffffffffu, c[w + 1], src);
                acc[w] += wv.x * ra + wv.y * rb + wv.z * rc;
                ra = rb; rb = rc;
            }
            acc[7] += wv.x * ra + wv.y * rb;
        }

        // interleaved zero slice: channel l+1, full row, sequential v8
        {
            float* p = zrow0 + (size_t)(l + 1) * (1024 * 1024);
            #pragma unroll
            for (int g = 0; g < 4; g++) stz8(p + g * 256);
        }

        const float pa = sA[l];
        #pragma unroll
        for (int w = 0; w < 8; w++) {
            const float y = (acc[w] >= 0.f) ? acc[w] : pa * acc[w];
            c[w] = y + c[w];                // residual, in place
        }
    }

    // ---- we = exp(relu(x - sigmoid(conv)))-1, masked; reuse x[] ----
    float partial = 0.f;
    #pragma unroll
    for (int w = 0; w < 8; w++) {
        const float sg = 1.f / (1.f + __expf(-c[w]));
        float sp = fmaxf(x[w] - sg, 0.f);
        if (hh == w) sp = 0.f;              // self mask
        float v = __expf(sp) - 1.f;         // sp >= 0
        if (!pvalid) v = 0.f;
        x[w] = v;
        partial += v;
    }
    sPS[pp][hh][co] = partial;
    __syncthreads();

    if (tid < 64) {
        const int th = tid >> 3, tc = tid & 7;
        const float s = sPS[0][th][tc] + sPS[1][th][tc] + sPS[2][th][tc] + sPS[3][th][tc];
        sInv[th][tc] = 1.f / (s + EPS_F);
    }
    __syncthreads();   // also orders zero stores before band overwrite

    // ---- band store: one 256-bit store of the 8 normalized floats ----
    if (pvalid) {
        const float inv = sInv[hh][co];
        float* dst = out +
            ((size_t)((b * 8 + co) * 1024 + (i * 8 + hh)) * 1024 + (size_t)j * 8);
        stcs8(dst, x[0]*inv, x[1]*inv, x[2]*inv, x[3]*inv,
                   x[4]*inv, x[5]*inv, x[6]*inv, x[7]*inv);
    }
}

extern "C" void kernel_launch(void* const* d_in, const int* in_sizes, int n_in,
                              void* d_out, int out_size) {
    const float* pw = (const float*)d_in[0];
    const float* cw = (const float*)d_in[1];
    const float* cb = (const float*)d_in[2];
    const float* pa = (const float*)d_in[3];
    sag_v8<<<1024, 256>>>(pw, cw, cb, pa, (float*)d_out);
}

// round 16
// speedup vs baseline: 1.1290x; 1.0430x over previous
#include <cuda_runtime.h>

#define NLAYERS 7
#define EPS_F 1e-5f

// Shapes (fixed by setup_inputs): bsz=8, C=8, QL=KL=128, A=8, cross_range=2
// pw / out: [64, 1024, 1024] f32;  conv_w: [7,8,8,1,3]; conv_b: [7,8]; prelu_a: [7]
//
// One CTA per (b, q), 6 CTAs/SM (wave tail: 136 CTAs instead of 284).
// Register-resident 7-layer residual conv via __shfl_sync. Zero fill is
// row-sequential float4 stores, one 8-store slice per conv layer so DRAM is
// fed continuously. x is NOT kept live through the conv (reloaded from
// global at the epilogue) to fit the 40-reg budget for 6 CTAs/SM.
// Band values overwrite their 8 floats after __syncthreads.

__device__ __forceinline__ void stcs4(float* p, float4 v) {
    asm volatile("st.global.cs.v4.f32 [%0], {%1,%2,%3,%4};"
                 :: "l"(p), "f"(v.x), "f"(v.y), "f"(v.z), "f"(v.w) : "memory");
}

__global__ __launch_bounds__(256, 6)
void sag_occ6(const float* __restrict__ pw,
              const float* __restrict__ conv_w,
              const float* __restrict__ conv_b,
              const float* __restrict__ prelu_a,
              float* __restrict__ out)
{
    __shared__ float4 sW4[NLAYERS][8][8];   // [l][ci][co] = (k0,k1,k2,_)
    __shared__ float  sB [NLAYERS][8];
    __shared__ float  sA [NLAYERS];
    __shared__ float  sPS[4][8][8];         // partial row sums [pp][hh][co]
    __shared__ float  sInv[8][8];           // 1/(rowsum+eps)   [hh][co]

    const int tid  = threadIdx.x;
    const int lane = tid & 31;
    const int wrp  = tid >> 5;              // warp id 0..7
    const int b = blockIdx.x >> 7;          // batch
    const int i = blockIdx.x & 127;         // query index
    const size_t base = ((size_t)(b * 8) * 1024 + (size_t)i * 8) * 1024;

    // zero-stream base: warp wrp owns row (channel s, agent-row wrp);
    // 8 contiguous 512B warp-stores cover the 4KB row
    float* zrow0 = out + base + (size_t)wrp * 1024 + lane * 4;
    const float4 z = make_float4(0.f, 0.f, 0.f, 0.f);

    // compute roles: slab = pp*8+hh (8 lanes per slab), co = lane&7
    const int co   = tid & 7;
    const int pp   = tid >> 6;
    const int hh   = (tid >> 3) & 7;
    const int doff = (pp < 2) ? (pp - 2) : (pp - 1);  // {-2,-1,1,2}
    const int j    = i + doff;
    const bool pvalid = (j >= 0) && (j < 128);

    const float* srcx = pw +
        ((size_t)((b * 8 + co) * 1024 + (i * 8 + hh)) * 1024 + (size_t)(pvalid ? j : 0) * 8);

    // ---- x load -> seeds c[] directly (x reloaded at epilogue) ----
    float c[8];
    {
        float4 v0 = make_float4(0.f,0.f,0.f,0.f), v1 = v0;
        if (pvalid) { v0 = *(const float4*)srcx; v1 = *(const float4*)(srcx + 4); }
        c[0]=v0.x; c[1]=v0.y; c[2]=v0.z; c[3]=v0.w;
        c[4]=v1.x; c[5]=v1.y; c[6]=v1.z; c[7]=v1.w;
    }

    // ---- zero slice 0: channel 0, full 4KB row per warp, sequential ----
    {
        float* p = zrow0;
        #pragma unroll
        for (int g = 0; g < 8; g++) stcs4(p + g * 128, z);
    }

    // ---- conv params -> SMEM ----
    for (int t = tid; t < NLAYERS * 64; t += 256) {
        const int l = t >> 6, rem = t & 63, wco = rem >> 3, wci = rem & 7;
        const float* s = conv_w + ((l * 8 + wco) * 8 + wci) * 3;
        sW4[l][wci][wco] = make_float4(s[0], s[1], s[2], 0.f);
    }
    if (tid < NLAYERS * 8) (&sB[0][0])[tid] = conv_b[tid];
    if (tid < NLAYERS)     sA[tid] = prelu_a[tid];
    __syncthreads();

    const int gbase = lane & 24;            // slab group base lane

    // ---- 7-layer residual conv, rolling 3-reg shuffle window ----
    #pragma unroll 1
    for (int l = 0; l < NLAYERS; l++) {
        const float bias = sB[l][co];
        float acc[8];
        #pragma unroll
        for (int w = 0; w < 8; w++) acc[w] = bias;

        #pragma unroll
        for (int ci = 0; ci < 8; ci++) {
            const float4 wv = sW4[l][ci][co];
            const int src = gbase | ci;
            float ra = __shfl_sync(0xffffffffu, c[0], src);
            float rb = __shfl_sync(0xffffffffu, c[1], src);
            acc[0] += wv.y * ra + wv.z * rb;
            #pragma unroll
            for (int w = 1; w < 7; w++) {
                const float rc = __shfl_sync(0xffffffffu, c[w + 1], src);
                acc[w] += wv.x * ra + wv.y * rb + wv.z * rc;
                ra = rb; rb = rc;
            }
            acc[7] += wv.x * ra + wv.y * rb;
        }

        // interleaved zero slice: channel l+1, full row, sequential
        {
            float* p = zrow0 + (size_t)(l + 1) * (1024 * 1024);
            #pragma unroll
            for (int g = 0; g < 8; g++) stcs4(p + g * 128, z);
        }

        const float pa = sA[l];
        #pragma unroll
        for (int w = 0; w < 8; w++) {
            const float y = (acc[w] >= 0.f) ? acc[w] : pa * acc[w];
            c[w] = y + c[w];                // residual, in place
        }
    }

    // ---- epilogue: reload x, we = exp(relu(x - sigmoid(conv)))-1 ----
    float4 x0 = make_float4(0.f,0.f,0.f,0.f), x1 = x0;
    if (pvalid) { x0 = *(const float4*)srcx; x1 = *(const float4*)(srcx + 4); }
    float xv[8] = {x0.x, x0.y, x0.z, x0.w, x1.x, x1.y, x1.z, x1.w};

    float partial = 0.f;
    #pragma unroll
    for (int w = 0; w < 8; w++) {
        const float sg = 1.f / (1.f + __expf(-c[w]));
        float sp = fmaxf(xv[w] - sg, 0.f);
        if (hh == w) sp = 0.f;              // self mask
        float v = __expf(sp) - 1.f;         // sp >= 0
        if (!pvalid) v = 0.f;
        c[w] = v;                           // c now holds we
        partial += v;
    }
    sPS[pp][hh][co] = partial;
    __syncthreads();

    if (tid < 64) {
        const int th = tid >> 3, tc = tid & 7;
        const float s = sPS[0][th][tc] + sPS[1][th][tc] + sPS[2][th][tc] + sPS[3][th][tc];
        sInv[th][tc] = 1.f / (s + EPS_F);
    }
    __syncthreads();   // also orders zero stores before band overwrite

    // ---- band store overwrites its 8 floats ----
    if (pvalid) {
        const float inv = sInv[hh][co];
        float* dst = out +
            ((size_t)((b * 8 + co) * 1024 + (i * 8 + hh)) * 1024 + (size_t)j * 8);
        stcs4(dst,     make_float4(c[0]*inv, c[1]*inv, c[2]*inv, c[3]*inv));
        stcs4(dst + 4, make_float4(c[4]*inv, c[5]*inv, c[6]*inv, c[7]*inv));
    }
}

extern "C" void kernel_launch(void* const* d_in, const int* in_sizes, int n_in,
                              void* d_out, int out_size) {
    const float* pw = (const float*)d_in[0];
    const float* cw = (const float*)d_in[1];
    const float* cb = (const float*)d_in[2];
    const float* pa = (const float*)d_in[3];
    sag_occ6<<<1024, 256>>>(pw, cw, cb, pa, (float*)d_out);
}